// round 13
// baseline (speedup 1.0000x reference)
#include <cuda_runtime.h>
#include <cuda_fp16.h>
#include <cstdint>

#define Bn 64
#define Ln 200
#define Dn 256
#define Kn 8
#define BLn (Bn*Ln)
#define EPSF 1e-5f
#define SCALEF 0.0625f
#define NTILES 400
#define NSM 148

// ---------------- device scratch ----------------
__device__ float  g_q[2*Bn*Dn];
__device__ float4 g_stats[2*BLn];
__device__ float  g_score[2*BLn*Kn];
__device__ float  g_qkh[2*BLn];
__device__ float  g_glog[2*BLn];
__device__ float  g_w[2*BLn];
__device__ __align__(16) __half g_Wh[Dn*Dn];
__device__ __align__(16) __half g_J[Kn*Dn];
__device__ float  g_u[Dn];
__device__ float  g_v[Dn];
__device__ float  g_c1[Kn], g_c2[Kn];
__device__ float  g_posJ[Ln*Kn];
__device__ unsigned int g_sync;

// ---------------- helpers ----------------
__device__ __forceinline__ float warpSum(float v){
#pragma unroll
  for(int o=16;o>0;o>>=1) v += __shfl_xor_sync(0xffffffffu, v, o);
  return v;
}
__device__ __forceinline__ void mma16816(float* d, const uint32_t* a, const uint32_t* b){
  asm volatile("mma.sync.aligned.m16n8k16.row.col.f32.f16.f16.f32 "
    "{%0,%1,%2,%3}, {%4,%5,%6,%7}, {%8,%9}, {%0,%1,%2,%3};"
    : "+f"(d[0]), "+f"(d[1]), "+f"(d[2]), "+f"(d[3])
    : "r"(a[0]), "r"(a[1]), "r"(a[2]), "r"(a[3]), "r"(b[0]), "r"(b[1]));
}
__device__ __forceinline__ void ldsm4(uint32_t* r, const __half* p){
  uint32_t a = (uint32_t)__cvta_generic_to_shared(p);
  asm volatile("ldmatrix.sync.aligned.m8n8.x4.shared.b16 {%0,%1,%2,%3}, [%4];"
    : "=r"(r[0]), "=r"(r[1]), "=r"(r[2]), "=r"(r[3]) : "r"(a));
}
__device__ __forceinline__ uint4 pack8h(float v0,float v1,float v2,float v3,
                                        float v4,float v5,float v6,float v7){
  uint4 o; __half2* p = (__half2*)&o;
  p[0] = __floats2half2_rn(v0,v1); p[1] = __floats2half2_rn(v2,v3);
  p[2] = __floats2half2_rn(v4,v5); p[3] = __floats2half2_rn(v6,v7);
  return o;
}

// ---------------- 1. prep kernel: one warp per job, no barriers ----------------
// jobs: [0,256) W' rows | [256,384) q | [384,392) J | [392,1992) posJ
__global__ __launch_bounds__(256) void k_small(
    const float* __restrict__ xl, const float* __restrict__ xg,
    const float* __restrict__ intent, const float* __restrict__ pos,
    const float* __restrict__ rou, const float* __restrict__ Ww,
    const float* __restrict__ Wb,
    const float* __restrict__ g1, const float* __restrict__ b1,
    const float* __restrict__ g2, const float* __restrict__ b2,
    const float* __restrict__ g3, const float* __restrict__ b3,
    const float* __restrict__ g4, const float* __restrict__ b4,
    const int* __restrict__ seq){
  if(blockIdx.x == 0 && threadIdx.x == 0) g_sync = 0;  // reset grid barrier
  int job = blockIdx.x*8 + (threadIdx.x>>5);
  int lane = threadIdx.x&31;
  int d0 = lane*8;
  if(job < 256){                       // ---- W' = g4*W row, u, v ----
    int n = job;
    float4 wa = *(const float4*)&Ww[n*Dn + d0];
    float4 wb = *(const float4*)&Ww[n*Dn + d0 + 4];
    float4 ga = *(const float4*)&g4[d0], gb = *(const float4*)&g4[d0+4];
    float4 ba = *(const float4*)&b4[d0], bbv = *(const float4*)&b4[d0+4];
    float p0=ga.x*wa.x, p1=ga.y*wa.y, p2=ga.z*wa.z, p3=ga.w*wa.w;
    float p4=gb.x*wb.x, p5=gb.y*wb.y, p6=gb.z*wb.z, p7=gb.w*wb.w;
    *(uint4*)&g_Wh[n*Dn + d0] = pack8h(p0,p1,p2,p3,p4,p5,p6,p7);
    float up = p0+p1+p2+p3+p4+p5+p6+p7;
    float vp = ba.x*wa.x+ba.y*wa.y+ba.z*wa.z+ba.w*wa.w
             + bbv.x*wb.x+bbv.y*wb.y+bbv.z*wb.z+bbv.w*wb.w;
    up = warpSum(up); vp = warpSum(vp);
    if(lane==0){ g_u[n] = up; g_v[n] = vp + Wb[n]; }
  } else if(job < 384){                // ---- q = ln3(...) ----
    int i = job - 256;
    int which = i/Bn; int b = i - which*Bn;
    const float* x = which ? xg : xl;
    int idx = seq[b] - 1;
    float v[8];
    const float* xr = &x[(size_t)(b*Ln+idx)*Dn + d0];
    const float* pr = &pos[idx*Dn + d0];
#pragma unroll
    for(int j=0;j<8;j++) v[j] = xr[j] + pr[j] + rou[d0+j];
    float s0=0.f, s1=0.f;
#pragma unroll
    for(int j=0;j<8;j++){ s0 += v[j]; s1 += v[j]*v[j]; }
    s0 = warpSum(s0); s1 = warpSum(s1);
    float mu = s0/Dn, var = s1/Dn - mu*mu;
    float rs = rsqrtf(var + EPSF);
    float o[8];
#pragma unroll
    for(int j=0;j<8;j++) o[j] = (v[j]-mu)*rs*g3[d0+j] + b3[d0+j];
    *(float4*)&g_q[i*Dn + d0]     = *(float4*)&o[0];
    *(float4*)&g_q[i*Dn + d0 + 4] = *(float4*)&o[4];
  } else if(job < 392){                // ---- J, c1, c2 ----
    int k = job - 384;
    float iv[8];
    *(float4*)&iv[0] = *(const float4*)&intent[k*Dn + d0];
    *(float4*)&iv[4] = *(const float4*)&intent[k*Dn + d0 + 4];
    float s0=0.f, s1=0.f;
#pragma unroll
    for(int j=0;j<8;j++){ s0 += iv[j]; s1 += iv[j]*iv[j]; }
    s0 = warpSum(s0); s1 = warpSum(s1);
    float mu = s0/Dn, var = s1/Dn - mu*mu;
    float rs = rsqrtf(var + EPSF);
    float Jv[8], c1p=0.f, c2p=0.f;
#pragma unroll
    for(int j=0;j<8;j++){
      float I2v = (iv[j]-mu)*rs*g2[d0+j] + b2[d0+j];
      Jv[j] = g1[d0+j]*I2v;
      c1p += Jv[j];
      c2p += b1[d0+j]*I2v;
    }
    *(uint4*)&g_J[k*Dn + d0] = pack8h(Jv[0],Jv[1],Jv[2],Jv[3],Jv[4],Jv[5],Jv[6],Jv[7]);
    c1p = warpSum(c1p); c2p = warpSum(c2p);
    if(lane==0){ g_c1[k] = c1p; g_c2[k] = c2p; }
  } else if(job < 1992){               // ---- posJ[l,k] ----
    int jj = job - 392;
    int l = jj>>3, k = jj&7;
    float iv[8], pj[8];
    *(float4*)&iv[0] = *(const float4*)&intent[k*Dn + d0];
    *(float4*)&iv[4] = *(const float4*)&intent[k*Dn + d0 + 4];
    *(float4*)&pj[0] = *(const float4*)&pos[l*Dn + d0];
    *(float4*)&pj[4] = *(const float4*)&pos[l*Dn + d0 + 4];
    float s0=0.f, s1=0.f;
#pragma unroll
    for(int j=0;j<8;j++){ s0 += iv[j]; s1 += iv[j]*iv[j]; }
    s0 = warpSum(s0); s1 = warpSum(s1);
    float mu = s0/Dn, var = s1/Dn - mu*mu;
    float rs = rsqrtf(var + EPSF);
    float dsum = 0.f;
#pragma unroll
    for(int j=0;j<8;j++){
      float I2v = (iv[j]-mu)*rs*g2[d0+j] + b2[d0+j];
      dsum += pj[j]*g1[d0+j]*I2v;
    }
    dsum = warpSum(dsum);
    if(lane==0) g_posJ[l*Kn + k] = dsum;
  }
}

// ---------------- 2. persistent: GEMM -> wsm -> out ----------------
#define ACH 4608
#define BCH 18432
#define ECH 1152
#define OFF_B   0
#define OFF_BE  147456
#define OFF_A   156672
#define OFF_Q0  193536
#define OFF_Q1  194560
#define OFF_U   195584
#define OFF_V   196608
#define OFF_ST  197632
#define OFF_C1  198656
#define OFF_C2  198688
#define OFF_CQ1 198720
#define OFF_CQ2 198728
#define OFF_RED 198736
#define GEMM_SMEM 199040

__global__ __launch_bounds__(512, 1) void k_gemm(
    const float* __restrict__ xl, const float* __restrict__ xg,
    const float* __restrict__ pos,
    const float* __restrict__ g4, const float* __restrict__ b4,
    const float* __restrict__ g5, const float* __restrict__ b5,
    float* __restrict__ out){
  extern __shared__ char smem[];
  __half* sBh  = (__half*)(smem + OFF_B);
  __half* sBeh = (__half*)(smem + OFF_BE);
  __half* sAh  = (__half*)(smem + OFF_A);
  float* s_q0  = (float*)(smem + OFF_Q0);
  float* s_q1  = (float*)(smem + OFF_Q1);
  float* s_u   = (float*)(smem + OFF_U);
  float* s_v   = (float*)(smem + OFF_V);
  float4* s_st = (float4*)(smem + OFF_ST);
  float* s_c1  = (float*)(smem + OFF_C1);
  float* s_c2  = (float*)(smem + OFF_C2);
  float* s_cq1 = (float*)(smem + OFF_CQ1);
  float* s_cq2 = (float*)(smem + OFF_CQ2);
  float* red   = (float*)(smem + OFF_RED);

  int tid = threadIdx.x, lane = tid&31, wid = tid>>5;
  int wm = wid&3, wn = wid>>2;
  int qr = lane>>2, qc = (lane&3)*2;
  int rowA = tid>>3, segA = tid&7;
  int chA = segA>>1, ccA = (segA&1)*32;

  // ---- first-tile prefetch (overlaps B load) ----
  float4 pf[8];
  {
    int rowG = blockIdx.x*64;
    int which = rowG / BLn;
    int rowL = rowG - which*BLn;
    const float* x = which ? xg : xl;
    const float* xr = &x[(size_t)(rowL+rowA)*Dn + segA*32];
#pragma unroll
    for(int u=0; u<4; u++){
      pf[2*u]   = ((const float4*)(xr + u*8))[0];
      pf[2*u+1] = ((const float4*)(xr + u*8))[1];
    }
  }

  // ---- startup: B + J + zeros + constants ----
#pragma unroll
  for(int it=0; it<16; it++){
    int idx = tid + it*512;
    int r = idx>>5, g = idx&31;
    *(uint4*)&sBh[(g>>3)*BCH + r*72 + (g&7)*8] = *(const uint4*)&g_Wh[r*Dn + g*8];
  }
  if(tid < 256){
    int r = tid>>5, g = tid&31;
    *(uint4*)&sBeh[(g>>3)*ECH + r*72 + (g&7)*8] = *(const uint4*)&g_J[r*Dn + g*8];
    s_u[tid] = g_u[tid];
    s_v[tid] = g_v[tid];
  } else if(tid < 448){
    int t2 = tid - 256;
    int r = 10 + (t2>>5), g = t2&31;
    uint4 z = make_uint4(0,0,0,0);
    *(uint4*)&sBeh[(g>>3)*ECH + r*72 + (g&7)*8] = z;
  }
  if(tid < 8){ s_c1[tid] = g_c1[tid]; s_c2[tid] = g_c2[tid]; }

  int arow = (lane&7) + ((lane>>3)&1)*8;
  int akoff = ((lane>>4)&1)*8;
  int brow = (lane&7) + ((lane>>4)&1)*8;
  int bkoff = ((lane>>3)&1)*8;

#pragma unroll 1
  for(int tile = blockIdx.x; tile < NTILES; tile += NSM){
    int rowG = tile*64;
    int which = rowG / BLn;
    int rowL = rowG - which*BLn;
    int b0 = rowL/Ln, b1 = (rowL+63)/Ln;
    int thr = (b0+1)*Ln - rowL;
    const float* x = which ? xg : xl;
    int qb0 = (which*Bn + b0)*Dn, qb1 = (which*Bn + b1)*Dn;

    __syncthreads();
    // ---- phase 1: prep + A pack (from pf) + stats + ext fill ----
    if(tid < 256) s_q0[tid] = g_q[qb0 + tid];
    else s_q1[tid-256] = g_q[qb1 + tid - 256];
    if(tid < 64) red[tid] = 0.f;
    {
      int gr = rowL + rowA;
      int lp = gr % Ln;
      const float* pr = &pos[lp*Dn + segA*32];
      float s0=0.f, s1=0.f, s2=0.f, s3=0.f;
#pragma unroll
      for(int u=0; u<4; u++){
        float4 xa = pf[2*u], xb = pf[2*u+1];
        float4 pa = ((const float4*)(pr + u*8))[0];
        float4 pb = ((const float4*)(pr + u*8))[1];
        float v0=xa.x+pa.x, v1=xa.y+pa.y, v2=xa.z+pa.z, v3=xa.w+pa.w;
        float v4=xb.x+pb.x, v5=xb.y+pb.y, v6=xb.z+pb.z, v7=xb.w+pb.w;
        s0 += xa.x+xa.y+xa.z+xa.w+xb.x+xb.y+xb.z+xb.w;
        s1 += xa.x*xa.x+xa.y*xa.y+xa.z*xa.z+xa.w*xa.w
            + xb.x*xb.x+xb.y*xb.y+xb.z*xb.z+xb.w*xb.w;
        s2 += v0+v1+v2+v3+v4+v5+v6+v7;
        s3 += v0*v0+v1*v1+v2*v2+v3*v3+v4*v4+v5*v5+v6*v6+v7*v7;
        *(uint4*)&sAh[chA*ACH + rowA*72 + ccA + u*8] = pack8h(v0,v1,v2,v3,v4,v5,v6,v7);
      }
#pragma unroll
      for(int o=1;o<8;o<<=1){
        s0 += __shfl_xor_sync(0xffffffffu, s0, o);
        s1 += __shfl_xor_sync(0xffffffffu, s1, o);
        s2 += __shfl_xor_sync(0xffffffffu, s2, o);
        s3 += __shfl_xor_sync(0xffffffffu, s3, o);
      }
      if(segA==0){
        float4 f;
        f.x = s0*(1.f/Dn); f.y = s1*(1.f/Dn) - f.x*f.x;
        f.z = s2*(1.f/Dn);
        float var2 = s3*(1.f/Dn) - f.z*f.z;
        f.w = rsqrtf(var2 + EPSF);
        s_st[rowA] = f;
        g_stats[which*BLn + rowL + rowA] = f;
      }
    }
    if(tid < 64){
      int r = 8 + (tid>>5);
      int ch = (tid>>3)&3, seg = tid&7;
      int dbase = ch*64 + seg*8;
      int qb = (r==8) ? qb0 : qb1;
      float4 qa = *(const float4*)&g_q[qb + dbase];
      float4 qv = *(const float4*)&g_q[qb + dbase + 4];
      float4 ga = *(const float4*)&g4[dbase], gb2 = *(const float4*)&g4[dbase+4];
      float4 ba = *(const float4*)&b4[dbase], bb2 = *(const float4*)&b4[dbase+4];
      float e0=ga.x*qa.x, e1=ga.y*qa.y, e2=ga.z*qa.z, e3=ga.w*qa.w;
      float e4=gb2.x*qv.x, e5=gb2.y*qv.y, e6=gb2.z*qv.z, e7=gb2.w*qv.w;
      *(uint4*)&sBeh[ch*ECH + r*72 + seg*8] = pack8h(e0,e1,e2,e3,e4,e5,e6,e7);
      float p1 = e0+e1+e2+e3+e4+e5+e6+e7;
      float p2 = ba.x*qa.x+ba.y*qa.y+ba.z*qa.z+ba.w*qa.w
               + bb2.x*qv.x+bb2.y*qv.y+bb2.z*qv.z+bb2.w*qv.w;
#pragma unroll
      for(int o=1;o<32;o<<=1){
        p1 += __shfl_xor_sync(0xffffffffu, p1, o);
        p2 += __shfl_xor_sync(0xffffffffu, p2, o);
      }
      if((tid&31)==0){ s_cq1[r-8] = p1; s_cq2[r-8] = p2; }
    }
    __syncthreads();

    // ---- prefetch next tile ----
    {
      int nt = tile + NSM;
      if(nt >= NTILES) nt = tile;
      int rowGn = nt*64;
      int whichn = rowGn / BLn;
      int rowLn2 = rowGn - whichn*BLn;
      const float* xn = whichn ? xg : xl;
      const float* xr = &xn[(size_t)(rowLn2+rowA)*Dn + segA*32];
#pragma unroll
      for(int u=0; u<4; u++){
        pf[2*u]   = ((const float4*)(xr + u*8))[0];
        pf[2*u+1] = ((const float4*)(xr + u*8))[1];
      }
    }

    // ---- phase 2: MMA + epilogue ----
    float acc[8][4];
#pragma unroll
    for(int t=0;t<8;t++)
#pragma unroll
      for(int c=0;c<4;c++) acc[t][c] = 0.f;
    float accE[8];
#pragma unroll
    for(int c=0;c<8;c++) accE[c] = 0.f;

#pragma unroll
    for(int c=0; c<4; c++){
      const __half* Ac = sAh + c*ACH;
      const __half* Bc = sBh + c*BCH;
      const __half* Ec = sBeh + c*ECH;
#pragma unroll
      for(int ks=0; ks<4; ks++){
        int kk = ks*16;
        uint32_t a0[4];
        ldsm4(a0, &Ac[(wm*16 + arow)*72 + kk + akoff]);
        if(wn==0){
          uint32_t be[4];
          ldsm4(be, &Ec[brow*72 + kk + bkoff]);
          mma16816(accE,   a0, be);
          mma16816(accE+4, a0, be+2);
        }
#pragma unroll
        for(int tp=0; tp<4; tp++){
          uint32_t bh[4];
          ldsm4(bh, &Bc[(wn*64 + tp*16 + brow)*72 + kk + bkoff]);
          mma16816(acc[tp*2],   a0, bh);
          mma16816(acc[tp*2+1], a0, bh+2);
        }
      }
    }
    {
      int r0 = wm*16 + qr, r1 = r0 + 8;
      float4 st0 = s_st[r0], st1 = s_st[r1];
      const float* q0p = (r0 < thr) ? s_q0 : s_q1;
      const float* q1p = (r1 < thr) ? s_q0 : s_q1;
      float p0 = 0.f, p1 = 0.f;
#pragma unroll
      for(int t=0; t<8; t++){
        int c0 = wn*64 + t*8 + qc;
        float2 uu = *(const float2*)&s_u[c0];
        float2 vv = *(const float2*)&s_v[c0];
        float2 qa = *(const float2*)&q0p[c0];
        float2 qb = *(const float2*)&q1p[c0];
        float e0 = st0.w*(acc[t][0] - st0.z*uu.x) + vv.x;
        float e1 = st0.w*(acc[t][1] - st0.z*uu.y) + vv.y;
        float e2 = st1.w*(acc[t][2] - st1.z*uu.x) + vv.x;
        float e3 = st1.w*(acc[t][3] - st1.z*uu.y) + vv.y;
        p0 += qa.x*fmaxf(e0,0.f) + qa.y*fmaxf(e1,0.f);
        p1 += qb.x*fmaxf(e2,0.f) + qb.y*fmaxf(e3,0.f);
      }
      p0 += __shfl_xor_sync(0xffffffffu, p0, 1);
      p0 += __shfl_xor_sync(0xffffffffu, p0, 2);
      p1 += __shfl_xor_sync(0xffffffffu, p1, 1);
      p1 += __shfl_xor_sync(0xffffffffu, p1, 2);
      if((lane&3)==0){
        atomicAdd(&red[r0], p0);
        atomicAdd(&red[r1], p1);
      }
    }
    __syncthreads();

    // ---- phase 3: glog write + ext epilogue ----
    if(tid < 64) g_glog[which*BLn + rowL + tid] = red[tid];
    if(wn==0){
      int base = lane & ~3;
      float sc0[8], sc1[8];
#pragma unroll
      for(int src=0; src<4; src++){
        sc0[2*src]   = __shfl_sync(0xffffffffu, accE[0], base+src);
        sc0[2*src+1] = __shfl_sync(0xffffffffu, accE[1], base+src);
        sc1[2*src]   = __shfl_sync(0xffffffffu, accE[2], base+src);
        sc1[2*src+1] = __shfl_sync(0xffffffffu, accE[3], base+src);
      }
      if((lane&3)==0){
#pragma unroll
        for(int half=0; half<2; half++){
          int r = wm*16 + qr + half*8;
          float* sc = half ? sc1 : sc0;
          float qdA = accE[4 + half*2];
          float qdB = accE[4 + half*2 + 1];
          float4 stv = s_st[r];
          float rs1 = rsqrtf(stv.y + EPSF);
          int rl = rowL + r;
          int bb = rl / Ln;
          int l = rl - bb*Ln;
          int gi = which*BLn + rl;
          float sraw[8];
          float m = -1e30f;
#pragma unroll
          for(int k=0;k<8;k++){
            sraw[k] = (rs1*(sc[k] - g_posJ[l*Kn+k] - stv.x*s_c1[k]) + s_c2[k])*SCALEF;
            m = fmaxf(m, sraw[k]);
          }
          float e[8], ss = 0.f;
#pragma unroll
          for(int k=0;k<8;k++){ e[k] = expf(sraw[k]-m); ss += e[k]; }
          float inv = 1.f/ss;
#pragma unroll
          for(int k=0;k<8;k++) g_score[gi*8+k] = e[k]*inv;
          int bsel = (r < thr) ? 0 : 1;
          float qd = bsel ? qdB : qdA;
          g_qkh[gi] = stv.w*(qd - stv.z*s_cq1[bsel]) + s_cq2[bsel];
        }
      }
    }
  }

  // ======== grid barrier 1 (gemm -> wsm) ========
  __threadfence();
  __syncthreads();
  if(tid == 0){
    atomicAdd(&g_sync, 1u);
    while(atomicAdd(&g_sync, 0u) < NSM) __nanosleep(128);
  }
  __syncthreads();
  __threadfence();

  // ---- fused softmax over L ----
  if(blockIdx.x < 2*Bn){
    int i = blockIdx.x;
    int which = i/Bn; int b = i - which*Bn;
    int t = tid;
    int rr = which*BLn + b*Ln + t;
    float v = (t < Ln) ? (g_glog[rr] + g_qkh[rr])*SCALEF : -1e30f;
    float* smr = red;
    int w = tid>>5, ln = tid&31;
    float m = v;
#pragma unroll
    for(int o=16;o>0;o>>=1) m = fmaxf(m, __shfl_xor_sync(0xffffffffu, m, o));
    if(ln==0) smr[w] = m;
    __syncthreads();
    if(tid==0){
      float mm = smr[0];
      for(int u=1;u<16;u++) mm = fmaxf(mm, smr[u]);
      smr[16] = mm;
    }
    __syncthreads();
    float mm = smr[16];
    float e = (t < Ln) ? expf(v - mm) : 0.f;
    float s = warpSum(e);
    __syncthreads();
    if(ln==0) smr[w] = s;
    __syncthreads();
    if(tid==0){
      float ss = 0.f;
      for(int u=0;u<16;u++) ss += smr[u];
      smr[16] = ss;
    }
    __syncthreads();
    if(t < Ln) g_w[rr] = e / smr[16];
  }

  // ======== grid barrier 2 (wsm -> out) ========
  __threadfence();
  __syncthreads();
  if(tid == 0){
    atomicAdd(&g_sync, 1u);
    while(atomicAdd(&g_sync, 0u) < 2u*NSM) __nanosleep(128);
  }
  __syncthreads();
  __threadfence();

  // ---- fused output: ln5(fuse*x) summed over branches ----
  {
    float* sAS = (float*)(smem + OFF_ST);   // 128 floats
#pragma unroll 1
    for(int rg = blockIdx.x; rg < BLn/8; rg += NSM){
      int row0 = rg*8;
      __syncthreads();
      if(tid < 128){
        int rl = tid>>4, idx = tid&15;
        int r2 = row0 + rl;
        int which = idx>>3, k = idx&7;
        int rr = which*BLn + r2;
        float f = g_score[rr*8 + k] * g_w[rr];
        float var = g_stats[which*BLn + r2].y;
        sAS[rl*16 + idx] = f * rsqrtf(f*f*var + EPSF);
      }
      __syncthreads();
      int rloc = tid>>6;               // 0..7
      int row = row0 + rloc;
      int d = (tid&63)*4;
      int b = row/Ln, l = row - b*Ln;
      float muL = g_stats[row].x, muG = g_stats[BLn + row].x;
      float4 xv = *(const float4*)&xl[(size_t)row*Dn + d];
      float4 gv = *(const float4*)&xg[(size_t)row*Dn + d];
      float4 g5v = *(const float4*)&g5[d];
      float4 b5v = *(const float4*)&b5[d];
      float dLx = xv.x-muL, dLy = xv.y-muL, dLz = xv.z-muL, dLw = xv.w-muL;
      float dGx = gv.x-muG, dGy = gv.y-muG, dGz = gv.z-muG, dGw = gv.w-muG;
      float bbx = 2.f*b5v.x, bby = 2.f*b5v.y, bbz = 2.f*b5v.z, bbw = 2.f*b5v.w;
      size_t base = (size_t)b*Kn*Ln*Dn + (size_t)l*Dn + d;
#pragma unroll
      for(int k=0;k<8;k++){
        float aL = sAS[rloc*16 + k], aG = sAS[rloc*16 + 8 + k];
        float4 v;
        v.x = (aL*dLx + aG*dGx)*g5v.x + bbx;
        v.y = (aL*dLy + aG*dGy)*g5v.y + bby;
        v.z = (aL*dLz + aG*dGz)*g5v.z + bbz;
        v.w = (aL*dLw + aG*dGw)*g5v.w + bbw;
        __stcs((float4*)&out[base + (size_t)k*Ln*Dn], v);
      }
    }
  }
}

// ---------------- launch ----------------
extern "C" void kernel_launch(void* const* d_in, const int* in_sizes, int n_in,
                              void* d_out, int out_size){
  const float* xl     = (const float*)d_in[0];
  const float* xg     = (const float*)d_in[1];
  const float* intent = (const float*)d_in[2];
  const float* pos    = (const float*)d_in[3];
  const float* rou    = (const float*)d_in[4];
  const float* Ww     = (const float*)d_in[5];
  const float* Wb     = (const float*)d_in[6];
  const float* g1 = (const float*)d_in[7];  const float* b1 = (const float*)d_in[8];
  const float* g2 = (const float*)d_in[9];  const float* b2 = (const float*)d_in[10];
  const float* g3 = (const float*)d_in[11]; const float* b3 = (const float*)d_in[12];
  const float* g4 = (const float*)d_in[13]; const float* b4 = (const float*)d_in[14];
  const float* g5 = (const float*)d_in[15]; const float* b5 = (const float*)d_in[16];
  const int*  seq = (const int*)d_in[17];
  float* out = (float*)d_out;

  static int configured = 0;
  if(!configured){
    cudaFuncSetAttribute(k_gemm, cudaFuncAttributeMaxDynamicSharedMemorySize, GEMM_SMEM);
    configured = 1;
  }

  k_small<<<249, 256>>>(xl, xg, intent, pos, rou, Ww, Wb,
                        g1, b1, g2, b2, g3, b3, g4, b4, seq);
  k_gemm<<<NSM, 512, GEMM_SMEM>>>(xl, xg, pos, g4, b4, g5, b5, out);
}

// round 14
// speedup vs baseline: 1.0744x; 1.0744x over previous
#include <cuda_runtime.h>
#include <cuda_fp16.h>
#include <cstdint>

#define Bn 64
#define Ln 200
#define Dn 256
#define Kn 8
#define BLn (Bn*Ln)
#define EPSF 1e-5f
#define SCALEF 0.0625f
#define NTILES 400
#define NSM 148

// ---------------- device scratch ----------------
__device__ float  g_q[2*Bn*Dn];
__device__ float4 g_stats[2*BLn];
__device__ float  g_score[2*BLn*Kn];
__device__ float  g_qkh[2*BLn];
__device__ float  g_glog[2*BLn];
__device__ float  g_w[2*BLn];
__device__ __align__(16) __half g_Wh[Dn*Dn];
__device__ __align__(16) __half g_J[Kn*Dn];
__device__ float  g_u[Dn];
__device__ float  g_v[Dn];
__device__ float  g_c1[Kn], g_c2[Kn];
__device__ float  g_posJ[Ln*Kn];
__device__ unsigned int g_sync;

// ---------------- helpers ----------------
__device__ __forceinline__ float warpSum(float v){
#pragma unroll
  for(int o=16;o>0;o>>=1) v += __shfl_xor_sync(0xffffffffu, v, o);
  return v;
}
__device__ __forceinline__ void mma16816(float* d, const uint32_t* a, const uint32_t* b){
  asm volatile("mma.sync.aligned.m16n8k16.row.col.f32.f16.f16.f32 "
    "{%0,%1,%2,%3}, {%4,%5,%6,%7}, {%8,%9}, {%0,%1,%2,%3};"
    : "+f"(d[0]), "+f"(d[1]), "+f"(d[2]), "+f"(d[3])
    : "r"(a[0]), "r"(a[1]), "r"(a[2]), "r"(a[3]), "r"(b[0]), "r"(b[1]));
}
__device__ __forceinline__ void ldsm4(uint32_t* r, const __half* p){
  uint32_t a = (uint32_t)__cvta_generic_to_shared(p);
  asm volatile("ldmatrix.sync.aligned.m8n8.x4.shared.b16 {%0,%1,%2,%3}, [%4];"
    : "=r"(r[0]), "=r"(r[1]), "=r"(r[2]), "=r"(r[3]) : "r"(a));
}
__device__ __forceinline__ uint4 pack8h(float v0,float v1,float v2,float v3,
                                        float v4,float v5,float v6,float v7){
  uint4 o; __half2* p = (__half2*)&o;
  p[0] = __floats2half2_rn(v0,v1); p[1] = __floats2half2_rn(v2,v3);
  p[2] = __floats2half2_rn(v4,v5); p[3] = __floats2half2_rn(v6,v7);
  return o;
}

// ---------------- 1. prep kernel: one warp per job ----------------
__global__ __launch_bounds__(256) void k_small(
    const float* __restrict__ xl, const float* __restrict__ xg,
    const float* __restrict__ intent, const float* __restrict__ pos,
    const float* __restrict__ rou, const float* __restrict__ Ww,
    const float* __restrict__ Wb,
    const float* __restrict__ g1, const float* __restrict__ b1,
    const float* __restrict__ g2, const float* __restrict__ b2,
    const float* __restrict__ g3, const float* __restrict__ b3,
    const float* __restrict__ g4, const float* __restrict__ b4,
    const int* __restrict__ seq){
  if(blockIdx.x == 0 && threadIdx.x == 0) g_sync = 0;
  int job = blockIdx.x*8 + (threadIdx.x>>5);
  int lane = threadIdx.x&31;
  int d0 = lane*8;
  if(job < 256){
    int n = job;
    float4 wa = *(const float4*)&Ww[n*Dn + d0];
    float4 wb = *(const float4*)&Ww[n*Dn + d0 + 4];
    float4 ga = *(const float4*)&g4[d0], gb = *(const float4*)&g4[d0+4];
    float4 ba = *(const float4*)&b4[d0], bbv = *(const float4*)&b4[d0+4];
    float p0=ga.x*wa.x, p1=ga.y*wa.y, p2=ga.z*wa.z, p3=ga.w*wa.w;
    float p4=gb.x*wb.x, p5=gb.y*wb.y, p6=gb.z*wb.z, p7=gb.w*wb.w;
    *(uint4*)&g_Wh[n*Dn + d0] = pack8h(p0,p1,p2,p3,p4,p5,p6,p7);
    float up = p0+p1+p2+p3+p4+p5+p6+p7;
    float vp = ba.x*wa.x+ba.y*wa.y+ba.z*wa.z+ba.w*wa.w
             + bbv.x*wb.x+bbv.y*wb.y+bbv.z*wb.z+bbv.w*wb.w;
    up = warpSum(up); vp = warpSum(vp);
    if(lane==0){ g_u[n] = up; g_v[n] = vp + Wb[n]; }
  } else if(job < 384){
    int i = job - 256;
    int which = i/Bn; int b = i - which*Bn;
    const float* x = which ? xg : xl;
    int idx = seq[b] - 1;
    float v[8];
    const float* xr = &x[(size_t)(b*Ln+idx)*Dn + d0];
    const float* pr = &pos[idx*Dn + d0];
#pragma unroll
    for(int j=0;j<8;j++) v[j] = xr[j] + pr[j] + rou[d0+j];
    float s0=0.f, s1=0.f;
#pragma unroll
    for(int j=0;j<8;j++){ s0 += v[j]; s1 += v[j]*v[j]; }
    s0 = warpSum(s0); s1 = warpSum(s1);
    float mu = s0/Dn, var = s1/Dn - mu*mu;
    float rs = rsqrtf(var + EPSF);
    float o[8];
#pragma unroll
    for(int j=0;j<8;j++) o[j] = (v[j]-mu)*rs*g3[d0+j] + b3[d0+j];
    *(float4*)&g_q[i*Dn + d0]     = *(float4*)&o[0];
    *(float4*)&g_q[i*Dn + d0 + 4] = *(float4*)&o[4];
  } else if(job < 392){
    int k = job - 384;
    float iv[8];
    *(float4*)&iv[0] = *(const float4*)&intent[k*Dn + d0];
    *(float4*)&iv[4] = *(const float4*)&intent[k*Dn + d0 + 4];
    float s0=0.f, s1=0.f;
#pragma unroll
    for(int j=0;j<8;j++){ s0 += iv[j]; s1 += iv[j]*iv[j]; }
    s0 = warpSum(s0); s1 = warpSum(s1);
    float mu = s0/Dn, var = s1/Dn - mu*mu;
    float rs = rsqrtf(var + EPSF);
    float Jv[8], c1p=0.f, c2p=0.f;
#pragma unroll
    for(int j=0;j<8;j++){
      float I2v = (iv[j]-mu)*rs*g2[d0+j] + b2[d0+j];
      Jv[j] = g1[d0+j]*I2v;
      c1p += Jv[j];
      c2p += b1[d0+j]*I2v;
    }
    *(uint4*)&g_J[k*Dn + d0] = pack8h(Jv[0],Jv[1],Jv[2],Jv[3],Jv[4],Jv[5],Jv[6],Jv[7]);
    c1p = warpSum(c1p); c2p = warpSum(c2p);
    if(lane==0){ g_c1[k] = c1p; g_c2[k] = c2p; }
  } else if(job < 1992){
    int jj = job - 392;
    int l = jj>>3, k = jj&7;
    float iv[8], pj[8];
    *(float4*)&iv[0] = *(const float4*)&intent[k*Dn + d0];
    *(float4*)&iv[4] = *(const float4*)&intent[k*Dn + d0 + 4];
    *(float4*)&pj[0] = *(const float4*)&pos[l*Dn + d0];
    *(float4*)&pj[4] = *(const float4*)&pos[l*Dn + d0 + 4];
    float s0=0.f, s1=0.f;
#pragma unroll
    for(int j=0;j<8;j++){ s0 += iv[j]; s1 += iv[j]*iv[j]; }
    s0 = warpSum(s0); s1 = warpSum(s1);
    float mu = s0/Dn, var = s1/Dn - mu*mu;
    float rs = rsqrtf(var + EPSF);
    float dsum = 0.f;
#pragma unroll
    for(int j=0;j<8;j++){
      float I2v = (iv[j]-mu)*rs*g2[d0+j] + b2[d0+j];
      dsum += pj[j]*g1[d0+j]*I2v;
    }
    dsum = warpSum(dsum);
    if(lane==0) g_posJ[l*Kn + k] = dsum;
  }
}

// ---------------- 2. persistent HMMA GEMM + fused wsm, 1024 threads ----------------
#define ACH 4608
#define BCH 18432
#define ECH 1152
#define OFF_B   0
#define OFF_BE  147456
#define OFF_A   156672
#define OFF_Q0  193536
#define OFF_Q1  194560
#define OFF_U   195584
#define OFF_V   196608
#define OFF_ST  197632
#define OFF_C1  198656
#define OFF_C2  198688
#define OFF_CQ1 198720
#define OFF_CQ2 198728
#define OFF_RED 198736
#define GEMM_SMEM 199040

__global__ __launch_bounds__(1024, 1) void k_gemm(
    const float* __restrict__ xl, const float* __restrict__ xg,
    const float* __restrict__ pos,
    const float* __restrict__ g4, const float* __restrict__ b4){
  extern __shared__ char smem[];
  __half* sBh  = (__half*)(smem + OFF_B);
  __half* sBeh = (__half*)(smem + OFF_BE);
  __half* sAh  = (__half*)(smem + OFF_A);
  float* s_q0  = (float*)(smem + OFF_Q0);
  float* s_q1  = (float*)(smem + OFF_Q1);
  float* s_u   = (float*)(smem + OFF_U);
  float* s_v   = (float*)(smem + OFF_V);
  float4* s_st = (float4*)(smem + OFF_ST);
  float* s_c1  = (float*)(smem + OFF_C1);
  float* s_c2  = (float*)(smem + OFF_C2);
  float* s_cq1 = (float*)(smem + OFF_CQ1);
  float* s_cq2 = (float*)(smem + OFF_CQ2);
  float* red   = (float*)(smem + OFF_RED);

  int tid = threadIdx.x, lane = tid&31, wid = tid>>5;
  int wm = wid&3, wn = wid>>2;          // 4m x 8n; warp tile 16 x 32
  int qr = lane>>2, qc = (lane&3)*2;
  int rowA = tid>>4, segA = tid&15;     // A fill: 64 rows x 16 segs of 16 cols
  int chA = segA>>2, ccA = (segA&3)*16;

  // ---- first-tile prefetch of x slice (16 floats) ----
  float4 pf[4];
  {
    int rowG = blockIdx.x*64;
    int which = rowG / BLn;
    int rowL = rowG - which*BLn;
    const float* x = which ? xg : xl;
    const float* xr = &x[(size_t)(rowL+rowA)*Dn + chA*64 + ccA];
#pragma unroll
    for(int u=0; u<4; u++) pf[u] = ((const float4*)xr)[u];
  }

  // ---- startup: B + J + zeros + constants ----
#pragma unroll
  for(int it=0; it<8; it++){
    int idx = tid + it*1024;
    int r = idx>>5, g = idx&31;
    *(uint4*)&sBh[(g>>3)*BCH + r*72 + (g&7)*8] = *(const uint4*)&g_Wh[r*Dn + g*8];
  }
  if(tid < 256){
    int r = tid>>5, g = tid&31;
    *(uint4*)&sBeh[(g>>3)*ECH + r*72 + (g&7)*8] = *(const uint4*)&g_J[r*Dn + g*8];
    s_u[tid] = g_u[tid];
    s_v[tid] = g_v[tid];
  } else if(tid < 448){
    int t2 = tid - 256;
    int r = 10 + (t2>>5), g = t2&31;
    uint4 z = make_uint4(0,0,0,0);
    *(uint4*)&sBeh[(g>>3)*ECH + r*72 + (g&7)*8] = z;
  }
  if(tid < 8){ s_c1[tid] = g_c1[tid]; s_c2[tid] = g_c2[tid]; }

  int arow = (lane&7) + ((lane>>3)&1)*8;
  int akoff = ((lane>>4)&1)*8;
  int brow = (lane&7) + ((lane>>4)&1)*8;
  int bkoff = ((lane>>3)&1)*8;

#pragma unroll 1
  for(int tile = blockIdx.x; tile < NTILES; tile += NSM){
    int rowG = tile*64;
    int which = rowG / BLn;
    int rowL = rowG - which*BLn;
    int b0 = rowL/Ln, b1 = (rowL+63)/Ln;
    int thr = (b0+1)*Ln - rowL;
    const float* x = which ? xg : xl;
    int qb0 = (which*Bn + b0)*Dn, qb1 = (which*Bn + b1)*Dn;

    __syncthreads();
    // ---- phase 1: q stage + A pack (from pf) + stats + ext fill ----
    if(tid < 256) s_q0[tid] = g_q[qb0 + tid];
    else if(tid < 512) s_q1[tid-256] = g_q[qb1 + tid - 256];
    if(tid < 64) red[tid] = 0.f;
    {
      int gr = rowL + rowA;
      int lp = gr % Ln;
      const float* pr = &pos[lp*Dn + chA*64 + ccA];
      float v[16];
      float s0=0.f, s1=0.f, s2=0.f, s3=0.f;
#pragma unroll
      for(int u=0; u<4; u++){
        float4 xa = pf[u];
        float4 pa = ((const float4*)pr)[u];
        float w0=xa.x+pa.x, w1=xa.y+pa.y, w2=xa.z+pa.z, w3=xa.w+pa.w;
        s0 += xa.x+xa.y+xa.z+xa.w;
        s1 += xa.x*xa.x+xa.y*xa.y+xa.z*xa.z+xa.w*xa.w;
        s2 += w0+w1+w2+w3;
        s3 += w0*w0+w1*w1+w2*w2+w3*w3;
        v[4*u]=w0; v[4*u+1]=w1; v[4*u+2]=w2; v[4*u+3]=w3;
      }
      *(uint4*)&sAh[chA*ACH + rowA*72 + ccA]     = pack8h(v[0],v[1],v[2],v[3],v[4],v[5],v[6],v[7]);
      *(uint4*)&sAh[chA*ACH + rowA*72 + ccA + 8] = pack8h(v[8],v[9],v[10],v[11],v[12],v[13],v[14],v[15]);
#pragma unroll
      for(int o=1;o<16;o<<=1){
        s0 += __shfl_xor_sync(0xffffffffu, s0, o);
        s1 += __shfl_xor_sync(0xffffffffu, s1, o);
        s2 += __shfl_xor_sync(0xffffffffu, s2, o);
        s3 += __shfl_xor_sync(0xffffffffu, s3, o);
      }
      if(segA==0){
        float4 f;
        f.x = s0*(1.f/Dn); f.y = s1*(1.f/Dn) - f.x*f.x;
        f.z = s2*(1.f/Dn);
        float var2 = s3*(1.f/Dn) - f.z*f.z;
        f.w = rsqrtf(var2 + EPSF);
        s_st[rowA] = f;
        g_stats[which*BLn + rowL + rowA] = f;
      }
    }
    if(tid < 64){  // ext rows 8,9 = g4*q(b0), g4*q(b1)
      int r = 8 + (tid>>5);
      int ch = (tid>>3)&3, seg = tid&7;
      int dbase = ch*64 + seg*8;
      int qb = (r==8) ? qb0 : qb1;
      float4 qa = *(const float4*)&g_q[qb + dbase];
      float4 qv = *(const float4*)&g_q[qb + dbase + 4];
      float4 ga = *(const float4*)&g4[dbase], gb2 = *(const float4*)&g4[dbase+4];
      float4 ba = *(const float4*)&b4[dbase], bb2 = *(const float4*)&b4[dbase+4];
      float e0=ga.x*qa.x, e1=ga.y*qa.y, e2=ga.z*qa.z, e3=ga.w*qa.w;
      float e4=gb2.x*qv.x, e5=gb2.y*qv.y, e6=gb2.z*qv.z, e7=gb2.w*qv.w;
      *(uint4*)&sBeh[ch*ECH + r*72 + seg*8] = pack8h(e0,e1,e2,e3,e4,e5,e6,e7);
      float p1 = e0+e1+e2+e3+e4+e5+e6+e7;
      float p2 = ba.x*qa.x+ba.y*qa.y+ba.z*qa.z+ba.w*qa.w
               + bb2.x*qv.x+bb2.y*qv.y+bb2.z*qv.z+bb2.w*qv.w;
#pragma unroll
      for(int o=1;o<32;o<<=1){
        p1 += __shfl_xor_sync(0xffffffffu, p1, o);
        p2 += __shfl_xor_sync(0xffffffffu, p2, o);
      }
      if((tid&31)==0){ s_cq1[r-8] = p1; s_cq2[r-8] = p2; }
    }
    __syncthreads();

    // ---- prefetch next tile ----
    {
      int nt = tile + NSM;
      if(nt >= NTILES) nt = tile;
      int rowGn = nt*64;
      int whichn = rowGn / BLn;
      int rowLn2 = rowGn - whichn*BLn;
      const float* xn = whichn ? xg : xl;
      const float* xr = &xn[(size_t)(rowLn2+rowA)*Dn + chA*64 + ccA];
#pragma unroll
      for(int u=0; u<4; u++) pf[u] = ((const float4*)xr)[u];
    }

    // ---- phase 2: MMA + epilogue ----
    float acc[4][4];
#pragma unroll
    for(int t=0;t<4;t++)
#pragma unroll
      for(int c=0;c<4;c++) acc[t][c] = 0.f;
    float accE[8];
#pragma unroll
    for(int c=0;c<8;c++) accE[c] = 0.f;

#pragma unroll
    for(int c=0; c<4; c++){
      const __half* Ac = sAh + c*ACH;
      const __half* Bc = sBh + c*BCH;
      const __half* Ec = sBeh + c*ECH;
#pragma unroll
      for(int ks=0; ks<4; ks++){
        int kk = ks*16;
        uint32_t a0[4];
        ldsm4(a0, &Ac[(wm*16 + arow)*72 + kk + akoff]);
        if(wn==0){
          uint32_t be[4];
          ldsm4(be, &Ec[brow*72 + kk + bkoff]);
          mma16816(accE,   a0, be);
          mma16816(accE+4, a0, be+2);
        }
#pragma unroll
        for(int tp=0; tp<2; tp++){
          uint32_t bh[4];
          ldsm4(bh, &Bc[(wn*32 + tp*16 + brow)*72 + kk + bkoff]);
          mma16816(acc[tp*2],   a0, bh);
          mma16816(acc[tp*2+1], a0, bh+2);
        }
      }
    }
    {
      int r0 = wm*16 + qr, r1 = r0 + 8;
      float4 st0 = s_st[r0], st1 = s_st[r1];
      const float* q0p = (r0 < thr) ? s_q0 : s_q1;
      const float* q1p = (r1 < thr) ? s_q0 : s_q1;
      float p0 = 0.f, p1 = 0.f;
#pragma unroll
      for(int t=0; t<4; t++){
        int c0 = wn*32 + t*8 + qc;
        float2 uu = *(const float2*)&s_u[c0];
        float2 vv = *(const float2*)&s_v[c0];
        float2 qa = *(const float2*)&q0p[c0];
        float2 qb = *(const float2*)&q1p[c0];
        float e0 = st0.w*(acc[t][0] - st0.z*uu.x) + vv.x;
        float e1 = st0.w*(acc[t][1] - st0.z*uu.y) + vv.y;
        float e2 = st1.w*(acc[t][2] - st1.z*uu.x) + vv.x;
        float e3 = st1.w*(acc[t][3] - st1.z*uu.y) + vv.y;
        p0 += qa.x*fmaxf(e0,0.f) + qa.y*fmaxf(e1,0.f);
        p1 += qb.x*fmaxf(e2,0.f) + qb.y*fmaxf(e3,0.f);
      }
      p0 += __shfl_xor_sync(0xffffffffu, p0, 1);
      p0 += __shfl_xor_sync(0xffffffffu, p0, 2);
      p1 += __shfl_xor_sync(0xffffffffu, p1, 1);
      p1 += __shfl_xor_sync(0xffffffffu, p1, 2);
      if((lane&3)==0){
        atomicAdd(&red[r0], p0);
        atomicAdd(&red[r1], p1);
      }
    }
    __syncthreads();

    // ---- phase 3: glog write + ext epilogue ----
    if(tid < 64) g_glog[which*BLn + rowL + tid] = red[tid];
    if(wn==0){
      int base = lane & ~3;
      float sc0[8], sc1[8];
#pragma unroll
      for(int src=0; src<4; src++){
        sc0[2*src]   = __shfl_sync(0xffffffffu, accE[0], base+src);
        sc0[2*src+1] = __shfl_sync(0xffffffffu, accE[1], base+src);
        sc1[2*src]   = __shfl_sync(0xffffffffu, accE[2], base+src);
        sc1[2*src+1] = __shfl_sync(0xffffffffu, accE[3], base+src);
      }
      if((lane&3)==0){
#pragma unroll
        for(int half=0; half<2; half++){
          int r = wm*16 + qr + half*8;
          float* sc = half ? sc1 : sc0;
          float qdA = accE[4 + half*2];
          float qdB = accE[4 + half*2 + 1];
          float4 stv = s_st[r];
          float rs1 = rsqrtf(stv.y + EPSF);
          int rl = rowL + r;
          int bb = rl / Ln;
          int l = rl - bb*Ln;
          int gi = which*BLn + rl;
          float sraw[8];
          float m = -1e30f;
#pragma unroll
          for(int k=0;k<8;k++){
            sraw[k] = (rs1*(sc[k] - g_posJ[l*Kn+k] - stv.x*s_c1[k]) + s_c2[k])*SCALEF;
            m = fmaxf(m, sraw[k]);
          }
          float e[8], ss = 0.f;
#pragma unroll
          for(int k=0;k<8;k++){ e[k] = expf(sraw[k]-m); ss += e[k]; }
          float inv = 1.f/ss;
#pragma unroll
          for(int k=0;k<8;k++) g_score[gi*8+k] = e[k]*inv;
          int bsel = (r < thr) ? 0 : 1;
          float qd = bsel ? qdB : qdA;
          g_qkh[gi] = stv.w*(qd - stv.z*s_cq1[bsel]) + s_cq2[bsel];
        }
      }
    }
  }

  // ---- grid barrier, then fused softmax-over-L ----
  __threadfence();
  __syncthreads();
  if(tid == 0){
    atomicAdd(&g_sync, 1u);
    while(atomicAdd(&g_sync, 0u) < NSM) __nanosleep(128);
  }
  __syncthreads();
  __threadfence();

  if(blockIdx.x < 2*Bn){
    int i = blockIdx.x;
    int which = i/Bn; int b = i - which*Bn;
    int t = tid;
    int rr = which*BLn + b*Ln + t;
    float v = (t < Ln) ? (g_glog[rr] + g_qkh[rr])*SCALEF : -1e30f;
    float* smr = red;
    int w = tid>>5, ln = tid&31;
    float m = v;
#pragma unroll
    for(int o=16;o>0;o>>=1) m = fmaxf(m, __shfl_xor_sync(0xffffffffu, m, o));
    if(ln==0) smr[w] = m;
    __syncthreads();
    if(tid==0){
      float mm = smr[0];
      for(int u=1;u<32;u++) mm = fmaxf(mm, smr[u]);
      smr[32] = mm;
    }
    __syncthreads();
    float mm = smr[32];
    float e = (t < Ln) ? expf(v - mm) : 0.f;
    float s = warpSum(e);
    __syncthreads();
    if(ln==0) smr[w] = s;
    __syncthreads();
    if(tid==0){
      float ss = 0.f;
      for(int u=0;u<32;u++) ss += smr[u];
      smr[32] = ss;
    }
    __syncthreads();
    if(t < Ln) g_w[rr] = e / smr[32];
  }
}

// ---------------- 3. output: ln5(fuse*x) summed over branches ----------------
__global__ __launch_bounds__(256) void k_out(
    const float* __restrict__ xl, const float* __restrict__ xg,
    const float* __restrict__ g5, const float* __restrict__ b5,
    float* __restrict__ out){
  int tid = threadIdx.x;
  int rloc = tid>>6;
  int row = blockIdx.x*4 + rloc;
  int d = (tid&63)*4;
  __shared__ float aS[4][16];
  if(tid < 64){
    int rl = tid>>4, idx = tid&15;
    int r2 = blockIdx.x*4 + rl;
    int which = idx>>3, k = idx&7;
    int rr = which*BLn + r2;
    float f = g_score[rr*8 + k] * g_w[rr];
    float var = which ? g_stats[BLn + r2].y : g_stats[r2].y;
    aS[rl][idx] = f * rsqrtf(f*f*var + EPSF);
  }
  __syncthreads();
  int b = row/Ln, l = row - b*Ln;
  float muL = g_stats[row].x, muG = g_stats[BLn + row].x;
  float4 xv = *(const float4*)&xl[row*Dn + d];
  float4 gv = *(const float4*)&xg[row*Dn + d];
  float4 g5v = *(const float4*)&g5[d];
  float4 b5v = *(const float4*)&b5[d];
  float dLx = xv.x-muL, dLy = xv.y-muL, dLz = xv.z-muL, dLw = xv.w-muL;
  float dGx = gv.x-muG, dGy = gv.y-muG, dGz = gv.z-muG, dGw = gv.w-muG;
  float bbx = 2.f*b5v.x, bby = 2.f*b5v.y, bbz = 2.f*b5v.z, bbw = 2.f*b5v.w;
  size_t base = (size_t)b*Kn*Ln*Dn + (size_t)l*Dn + d;
#pragma unroll
  for(int k=0;k<8;k++){
    float aL = aS[rloc][k], aG = aS[rloc][8+k];
    float4 v;
    v.x = (aL*dLx + aG*dGx)*g5v.x + bbx;
    v.y = (aL*dLy + aG*dGy)*g5v.y + bby;
    v.z = (aL*dLz + aG*dGz)*g5v.z + bbz;
    v.w = (aL*dLw + aG*dGw)*g5v.w + bbw;
    __stcs((float4*)&out[base + (size_t)k*Ln*Dn], v);
  }
}

// ---------------- launch ----------------
extern "C" void kernel_launch(void* const* d_in, const int* in_sizes, int n_in,
                              void* d_out, int out_size){
  const float* xl     = (const float*)d_in[0];
  const float* xg     = (const float*)d_in[1];
  const float* intent = (const float*)d_in[2];
  const float* pos    = (const float*)d_in[3];
  const float* rou    = (const float*)d_in[4];
  const float* Ww     = (const float*)d_in[5];
  const float* Wb     = (const float*)d_in[6];
  const float* g1 = (const float*)d_in[7];  const float* b1 = (const float*)d_in[8];
  const float* g2 = (const float*)d_in[9];  const float* b2 = (const float*)d_in[10];
  const float* g3 = (const float*)d_in[11]; const float* b3 = (const float*)d_in[12];
  const float* g4 = (const float*)d_in[13]; const float* b4 = (const float*)d_in[14];
  const float* g5 = (const float*)d_in[15]; const float* b5 = (const float*)d_in[16];
  const int*  seq = (const int*)d_in[17];
  float* out = (float*)d_out;

  static int configured = 0;
  if(!configured){
    cudaFuncSetAttribute(k_gemm, cudaFuncAttributeMaxDynamicSharedMemorySize, GEMM_SMEM);
    configured = 1;
  }

  k_small<<<249, 256>>>(xl, xg, intent, pos, rou, Ww, Wb,
                        g1, b1, g2, b2, g3, b3, g4, b4, seq);
  k_gemm<<<NSM, 1024, GEMM_SMEM>>>(xl, xg, pos, g4, b4);
  k_out<<<BLn/4, 256>>>(xl, xg, g5, b5, out);
}